// round 2
// baseline (speedup 1.0000x reference)
#include <cuda_runtime.h>
#include <cstdint>
#include <cstddef>

// Problem constants
#define BB   64
#define TT   1000
#define DI   128
#define RR   512
#define OO   64
#define ALPHA 0.1f            // DT/TAU

// Scan kernel layout: 16 clusters x 8 CTAs, 4 batches/cluster, 64 neurons/CTA
#define CSIZE 8
#define NCLUS 16
#define BPC   4
#define NTHR  512

// ---------------------------------------------------------------------------
// Persistent scan kernel: one cluster = 4 batches, full recurrence T=1000.
// Each CTA (rank w) owns neurons [64w, 64w+64). Wrr/Wrx slices live in
// registers. r (4 batches x 512) lives in SMEM as [k] float4 rows (one float
// per batch), double-buffered; exchanged across the cluster via the rstore
// global writes + barrier.cluster (release/acquire) + __ldcg refill.
// ---------------------------------------------------------------------------
__global__ void __cluster_dims__(CSIZE, 1, 1) __launch_bounds__(NTHR, 1)
ctrnn_scan(const float* __restrict__ g_in,   // [B][T][DI]
           const float* __restrict__ g_br,   // [B][T][RR]
           const float* __restrict__ g_Wrx,  // [RR][DI]
           const float* __restrict__ g_bx,   // [RR]
           const float* __restrict__ g_Wrr,  // [RR][RR]
           const float* __restrict__ g_r0,   // [RR]
           float* __restrict__ g_rstore)     // [B][T][RR]
{
    __shared__ float4 rbuf[2][RR];   // [buf][k] = (r[b0..b3])   16 KB
    __shared__ float4 sInp[DI];      // [i] = (x[b0..b3])         2 KB
    __shared__ float4 pz[8][64];     // [kgroup][j] partials      8 KB

    const int w   = blockIdx.x;      // cluster rank 0..7
    const int c   = blockIdx.y;      // cluster id 0..15
    const int tid = threadIdx.x;
    const int j   = tid & 63;        // local neuron
    const int kg  = tid >> 6;        // k-group 0..7 (64 k each)
    const int jg  = w * 64 + j;      // global neuron
    const int b0  = c * BPC;         // first batch of this cluster

    // ---- one-time load of weight slices into registers ----
    float wrr[64];
    {
        const float4* src = (const float4*)(g_Wrr + (size_t)jg * RR + kg * 64);
        #pragma unroll
        for (int q = 0; q < 16; q++) {
            float4 v = src[q];
            wrr[4*q+0] = v.x; wrr[4*q+1] = v.y; wrr[4*q+2] = v.z; wrr[4*q+3] = v.w;
        }
    }
    float wrx[16];
    {
        const float4* src = (const float4*)(g_Wrx + (size_t)jg * DI + kg * 16);
        #pragma unroll
        for (int q = 0; q < 4; q++) {
            float4 v = src[q];
            wrx[4*q+0] = v.x; wrx[4*q+1] = v.y; wrx[4*q+2] = v.z; wrx[4*q+3] = v.w;
        }
    }
    const float bxr = g_bx[jg];

    // role indices
    const int rb  = tid >> 6;        // reducer batch (valid for tid<256)
    const int fb  = tid & 3;         // refill batch
    const int fk  = tid >> 2;        // refill k-chunk 0..127
    const int ib  = tid & 3;         // input-stage batch (tid<128)
    const int ii4 = tid >> 2;        // input-stage float4 chunk 0..31

    // init r buffer 0 from r0 (broadcast across the 4 batches)
    {
        float v = g_r0[tid];
        rbuf[0][tid] = make_float4(v, v, v, v);
    }
    __syncthreads();

    // prefetch input for t=0
    float4 nxt_in = make_float4(0.f, 0.f, 0.f, 0.f);
    if (tid < 128)
        nxt_in = *(const float4*)(g_in + (((size_t)(b0 + ib)) * TT + 0) * DI + ii4 * 4);

    int p = 0;
    for (int t = 0; t < TT; t++) {
        // ---- stage input[t] into SMEM transposed to [i][b] ----
        if (tid < 128) {
            float* s = (float*)sInp;
            int i0 = ii4 * 4;
            s[(i0+0)*4 + ib] = nxt_in.x;
            s[(i0+1)*4 + ib] = nxt_in.y;
            s[(i0+2)*4 + ib] = nxt_in.z;
            s[(i0+3)*4 + ib] = nxt_in.w;
        }
        // prefetch br[t] (consumed in the reduce phase)
        float brv = 0.f;
        if (tid < 256)
            brv = g_br[(((size_t)(b0 + rb)) * TT + t) * RR + jg];
        __syncthreads();

        // prefetch next input while the GEMM runs
        if (tid < 128 && (t + 1) < TT)
            nxt_in = *(const float4*)(g_in + (((size_t)(b0 + ib)) * TT + (t + 1)) * DI + ii4 * 4);

        // ---- main compute: z[b] partial over my (j, k-slice) ----
        unsigned long long a01 = 0ull, a23 = 0ull;   // packed f32x2 accumulators
        {
            unsigned rbase = (unsigned)__cvta_generic_to_shared(&rbuf[p][kg * 64]);
            #pragma unroll
            for (int kk = 0; kk < 64; kk++) {
                unsigned long long r01, r23, ww;
                asm volatile("ld.shared.v2.u64 {%0,%1},[%2];"
                             : "=l"(r01), "=l"(r23) : "r"(rbase + 16 * kk));
                unsigned wu = __float_as_uint(wrr[kk]);
                asm("mov.b64 %0,{%1,%1};" : "=l"(ww) : "r"(wu));
                asm("fma.rn.f32x2 %0,%1,%2,%0;" : "+l"(a01) : "l"(ww), "l"(r01));
                asm("fma.rn.f32x2 %0,%1,%2,%0;" : "+l"(a23) : "l"(ww), "l"(r23));
            }
            unsigned ibase = (unsigned)__cvta_generic_to_shared(&sInp[kg * 16]);
            #pragma unroll
            for (int q = 0; q < 16; q++) {
                unsigned long long r01, r23, ww;
                asm volatile("ld.shared.v2.u64 {%0,%1},[%2];"
                             : "=l"(r01), "=l"(r23) : "r"(ibase + 16 * q));
                unsigned wu = __float_as_uint(wrx[q]);
                asm("mov.b64 %0,{%1,%1};" : "=l"(ww) : "r"(wu));
                asm("fma.rn.f32x2 %0,%1,%2,%0;" : "+l"(a01) : "l"(ww), "l"(r01));
                asm("fma.rn.f32x2 %0,%1,%2,%0;" : "+l"(a23) : "l"(ww), "l"(r23));
            }
        }
        {
            unsigned u0, u1, u2, u3;
            asm("mov.b64 {%0,%1},%2;" : "=r"(u0), "=r"(u1) : "l"(a01));
            asm("mov.b64 {%0,%1},%2;" : "=r"(u2), "=r"(u3) : "l"(a23));
            pz[kg][j] = make_float4(__uint_as_float(u0), __uint_as_float(u1),
                                    __uint_as_float(u2), __uint_as_float(u3));
        }
        __syncthreads();

        // ---- reduce k-groups, nonlinearity, state update, write rstore ----
        if (tid < 256) {
            float z = bxr;
            #pragma unroll
            for (int g = 0; g < 8; g++)
                z += ((const float*)&pz[g][j])[rb];
            float f = (z > 0.f) ? tanhf(z) : 0.f;          // retanh
            float rold = ((const float*)&rbuf[p][jg])[rb];
            float rn = fmaf(ALPHA, f + brv - rold, rold);  // r + a*(-r + f + br)
            g_rstore[(((size_t)(b0 + rb)) * TT + t) * RR + jg] = rn;
        }

        // ---- cluster barrier: release my rstore slice, acquire peers' ----
        asm volatile("barrier.cluster.arrive.aligned;" ::: "memory");
        asm volatile("barrier.cluster.wait.aligned;"   ::: "memory");

        // ---- refill the other r buffer with the full new r (all 8 slices) ----
        {
            float4 v = __ldcg((const float4*)(g_rstore +
                         (((size_t)(b0 + fb)) * TT + t) * RR + fk * 4));
            float* s = (float*)rbuf[p ^ 1];
            int k0 = fk * 4;
            s[(k0+0)*4 + fb] = v.x;
            s[(k0+1)*4 + fb] = v.y;
            s[(k0+2)*4 + fb] = v.z;
            s[(k0+3)*4 + fb] = v.w;
        }
        __syncthreads();
        p ^= 1;
    }
}

// ---------------------------------------------------------------------------
// Output GEMM: y[m][o] = by[o] + sum_k rstore[m][k] * Wyr[o][k]
// m = b*T + t (64000 rows). 64-row x 64-col tile per CTA, BK=32, 4x4 microtile
// with f32x2 accumulation.
// ---------------------------------------------------------------------------
#define YBM 64
#define YBK 32

__global__ void __launch_bounds__(256)
ctrnn_y(const float* __restrict__ g_rstore,  // [64000][512]
        const float* __restrict__ g_Wyr,     // [64][512]
        const float* __restrict__ g_by,      // [64]
        float* __restrict__ g_y)             // [64000][64]
{
    __shared__ float As[YBM][36];    // [m][k], pad 36 for conflict-free col reads
    __shared__ float Bs[YBK][OO];    // [k][n]

    const int tid = threadIdx.x;
    const int m0  = blockIdx.x * YBM;
    const int tx  = tid & 15;        // n-group (4 cols each)
    const int ty  = tid >> 4;        // m-group (4 rows each)

    unsigned long long acc[4][2];
    #pragma unroll
    for (int i = 0; i < 4; i++) { acc[i][0] = 0ull; acc[i][1] = 0ull; }

    for (int k0 = 0; k0 < RR; k0 += YBK) {
        // load rstore tile [64][32] -> As, float4 x2 per thread
        #pragma unroll
        for (int q = 0; q < 2; q++) {
            int idx = tid * 2 + q;           // 0..511
            int m   = idx >> 3;              // 0..63
            int kq  = idx & 7;               // 0..7 (float4 chunks)
            float4 v = *(const float4*)(g_rstore + (size_t)(m0 + m) * RR + k0 + kq * 4);
            *(float4*)&As[m][kq * 4] = v;
        }
        // load Wyr tile transposed -> Bs[k][n]
        #pragma unroll
        for (int q = 0; q < 2; q++) {
            int n  = tid >> 2;               // 0..63
            int kq = (tid & 3) * 2 + q;      // 0..7
            float4 v = *(const float4*)(g_Wyr + (size_t)n * RR + k0 + kq * 4);
            Bs[kq*4+0][n] = v.x;
            Bs[kq*4+1][n] = v.y;
            Bs[kq*4+2][n] = v.z;
            Bs[kq*4+3][n] = v.w;
        }
        __syncthreads();

        #pragma unroll
        for (int k = 0; k < YBK; k++) {
            unsigned long long bp0 = *(const unsigned long long*)&Bs[k][tx * 4];
            unsigned long long bp1 = *(const unsigned long long*)&Bs[k][tx * 4 + 2];
            #pragma unroll
            for (int i = 0; i < 4; i++) {
                unsigned au = __float_as_uint(As[ty * 4 + i][k]);
                unsigned long long ap;
                asm("mov.b64 %0,{%1,%1};" : "=l"(ap) : "r"(au));
                asm("fma.rn.f32x2 %0,%1,%2,%0;" : "+l"(acc[i][0]) : "l"(ap), "l"(bp0));
                asm("fma.rn.f32x2 %0,%1,%2,%0;" : "+l"(acc[i][1]) : "l"(ap), "l"(bp1));
            }
        }
        __syncthreads();
    }

    // epilogue: unpack, add bias, store
    float by0 = g_by[tx * 4 + 0];
    float by1 = g_by[tx * 4 + 1];
    float by2 = g_by[tx * 4 + 2];
    float by3 = g_by[tx * 4 + 3];
    #pragma unroll
    for (int i = 0; i < 4; i++) {
        unsigned u0, u1, u2, u3;
        asm("mov.b64 {%0,%1},%2;" : "=r"(u0), "=r"(u1) : "l"(acc[i][0]));
        asm("mov.b64 {%0,%1},%2;" : "=r"(u2), "=r"(u3) : "l"(acc[i][1]));
        float4 out = make_float4(__uint_as_float(u0) + by0,
                                 __uint_as_float(u1) + by1,
                                 __uint_as_float(u2) + by2,
                                 __uint_as_float(u3) + by3);
        *(float4*)(g_y + (size_t)(m0 + ty * 4 + i) * OO + tx * 4) = out;
    }
}

// ---------------------------------------------------------------------------
// Launch: scan (persistent cluster kernel) then output GEMM.
// Output layout assumed: [ y (B*T*OO) | rstore (B*T*RR) ]
// ---------------------------------------------------------------------------
extern "C" void kernel_launch(void* const* d_in, const int* in_sizes, int n_in,
                              void* d_out, int out_size)
{
    const float* input = (const float*)d_in[0];
    const float* br    = (const float*)d_in[1];
    const float* Wrx   = (const float*)d_in[2];
    const float* bx    = (const float*)d_in[3];
    const float* Wrr   = (const float*)d_in[4];
    const float* Wyr   = (const float*)d_in[5];
    const float* by    = (const float*)d_in[6];
    const float* r0    = (const float*)d_in[7];

    float* y      = (float*)d_out;
    float* rstore = (float*)d_out + (size_t)BB * TT * OO;

    dim3 grid(CSIZE, NCLUS, 1);
    ctrnn_scan<<<grid, NTHR>>>(input, br, Wrx, bx, Wrr, r0, rstore);

    ctrnn_y<<<(BB * TT) / YBM, 256>>>(rstore, Wyr, by, y);
}

// round 3
// speedup vs baseline: 1.0080x; 1.0080x over previous
#include <cuda_runtime.h>
#include <cstdint>
#include <cstddef>

// Problem constants
#define BB   64
#define TT   1000
#define DI   128
#define RR   512
#define OO   64
#define ALPHA 0.1f            // DT/TAU

// Scan layout: 16 clusters x 8 CTAs, 4 batches/cluster, 64 neurons/CTA
#define CSIZE 8
#define NCLUS 16
#define BPC   4
#define NTHR  512

__device__ __forceinline__ unsigned long long pack2(float a, float b) {
    unsigned long long r;
    asm("mov.b64 %0, {%1,%2};" : "=l"(r) : "r"(__float_as_uint(a)), "r"(__float_as_uint(b)));
    return r;
}
__device__ __forceinline__ float unpack_sum(unsigned long long v) {
    unsigned lo, hi;
    asm("mov.b64 {%0,%1}, %2;" : "=r"(lo), "=r"(hi) : "l"(v));
    return __uint_as_float(lo) + __uint_as_float(hi);
}

// ---------------------------------------------------------------------------
// Persistent scan kernel over t in [t0, t1). One cluster = 4 batches.
// CTA rank w owns neurons [64w, 64w+64); Wrr/Wrx slices live in registers as
// pre-packed f32x2 pairs. r lives in SMEM as [batch][k] (double-buffered).
// Cross-CTA exchange: reducers push the new r directly into all 8 CTAs'
// next buffer via st.shared::cluster; barrier.cluster orders it.
// ---------------------------------------------------------------------------
__global__ void __cluster_dims__(CSIZE, 1, 1) __launch_bounds__(NTHR, 1)
ctrnn_scan(const float* __restrict__ g_in,   // [B][T][DI]
           const float* __restrict__ g_br,   // [B][T][RR]
           const float* __restrict__ g_Wrx,  // [RR][DI]
           const float* __restrict__ g_bx,   // [RR]
           const float* __restrict__ g_Wrr,  // [RR][RR]
           const float* __restrict__ g_r0,   // [RR]
           float* __restrict__ g_rstore,     // [B][T][RR]
           int t0, int t1)
{
    __shared__ __align__(16) float rbuf[2][BPC][RR];   // 16 KB
    __shared__ __align__(16) float sInp[BPC][DI];      //  2 KB
    __shared__ __align__(16) float4 pz[8][64];         //  8 KB

    const int w   = blockIdx.x;      // cluster rank 0..7
    const int c   = blockIdx.y;      // cluster id 0..15
    const int tid = threadIdx.x;
    const int j   = tid & 63;        // local neuron
    const int kg  = tid >> 6;        // k-group 0..7 (64 k each)
    const int jg  = w * 64 + j;      // global neuron
    const int b0  = c * BPC;         // first batch of this cluster

    // ---- one-time: weight slices into registers as packed pairs ----
    unsigned long long wrrp[32];
    {
        const float4* src = (const float4*)(g_Wrr + (size_t)jg * RR + kg * 64);
        #pragma unroll
        for (int q = 0; q < 16; q++) {
            float4 v = src[q];
            wrrp[2*q+0] = pack2(v.x, v.y);
            wrrp[2*q+1] = pack2(v.z, v.w);
        }
    }
    unsigned long long wrxp[8];
    {
        const float4* src = (const float4*)(g_Wrx + (size_t)jg * DI + kg * 16);
        #pragma unroll
        for (int q = 0; q < 4; q++) {
            float4 v = src[q];
            wrxp[2*q+0] = pack2(v.x, v.y);
            wrxp[2*q+1] = pack2(v.z, v.w);
        }
    }
    const float bxr = g_bx[jg];

    // role indices
    const int rb  = tid >> 6;        // reducer batch (tid<256)
    const int sb  = tid >> 5;        // input-stage batch (tid<128): 0..3
    const int si4 = tid & 31;        // input-stage float4 chunk

    // ---- init r buffer 0 ----
    if (t0 == 0) {
        float v = g_r0[tid];
        #pragma unroll
        for (int b = 0; b < BPC; b++) rbuf[0][b][tid] = v;
    } else {
        #pragma unroll
        for (int b = 0; b < BPC; b++)
            rbuf[0][b][tid] = g_rstore[(((size_t)(b0 + b)) * TT + (t0 - 1)) * RR + tid];
    }
    __syncthreads();

    // prefetch input for t0
    float4 nxt_in = make_float4(0.f, 0.f, 0.f, 0.f);
    if (tid < 128)
        nxt_in = *(const float4*)(g_in + (((size_t)(b0 + sb)) * TT + t0) * DI + si4 * 4);

    int p = 0;
    for (int t = t0; t < t1; t++) {
        // ---- stage input[t] into SMEM [b][i] (straight copy) ----
        if (tid < 128)
            *(float4*)&sInp[sb][si4 * 4] = nxt_in;
        // prefetch br[t] (consumed in the reduce phase)
        float brv = 0.f;
        if (tid < 256)
            brv = g_br[(((size_t)(b0 + rb)) * TT + t) * RR + jg];
        __syncthreads();

        // prefetch next input while the GEMM runs
        if (tid < 128 && (t + 1) < TT)
            nxt_in = *(const float4*)(g_in + (((size_t)(b0 + sb)) * TT + (t + 1)) * DI + si4 * 4);

        // ---- main compute: packed-pair matvec over my (j, k-slice) ----
        unsigned long long acc[4] = {0ull, 0ull, 0ull, 0ull};
        {
            // Wrr part: 64 k in 16 chunks of 4
            unsigned rbase = (unsigned)__cvta_generic_to_shared(&rbuf[p][0][kg * 64]);
            #pragma unroll
            for (int ch = 0; ch < 16; ch++) {
                #pragma unroll
                for (int b = 0; b < 4; b++) {
                    unsigned long long p0, p1;
                    asm volatile("ld.shared.v2.u64 {%0,%1},[%2];"
                                 : "=l"(p0), "=l"(p1)
                                 : "r"(rbase + b * (RR * 4) + ch * 16));
                    asm("fma.rn.f32x2 %0,%1,%2,%0;" : "+l"(acc[b]) : "l"(wrrp[2*ch+0]), "l"(p0));
                    asm("fma.rn.f32x2 %0,%1,%2,%0;" : "+l"(acc[b]) : "l"(wrrp[2*ch+1]), "l"(p1));
                }
            }
            // Wrx part: 16 i in 4 chunks of 4
            unsigned ibase = (unsigned)__cvta_generic_to_shared(&sInp[0][kg * 16]);
            #pragma unroll
            for (int ch = 0; ch < 4; ch++) {
                #pragma unroll
                for (int b = 0; b < 4; b++) {
                    unsigned long long p0, p1;
                    asm volatile("ld.shared.v2.u64 {%0,%1},[%2];"
                                 : "=l"(p0), "=l"(p1)
                                 : "r"(ibase + b * (DI * 4) + ch * 16));
                    asm("fma.rn.f32x2 %0,%1,%2,%0;" : "+l"(acc[b]) : "l"(wrxp[2*ch+0]), "l"(p0));
                    asm("fma.rn.f32x2 %0,%1,%2,%0;" : "+l"(acc[b]) : "l"(wrxp[2*ch+1]), "l"(p1));
                }
            }
        }
        pz[kg][j] = make_float4(unpack_sum(acc[0]), unpack_sum(acc[1]),
                                unpack_sum(acc[2]), unpack_sum(acc[3]));
        __syncthreads();

        const int pn = p ^ 1;
        // ---- reduce k-groups, nonlinearity, state update ----
        if (tid < 256) {
            float z = bxr;
            #pragma unroll
            for (int g = 0; g < 8; g++)
                z += ((const float*)&pz[g][j])[rb];
            float f = (z > 0.f) ? tanhf(z) : 0.f;          // retanh
            float rold = rbuf[p][rb][jg];
            float rn = fmaf(ALPHA, f + brv - rold, rold);  // r + a*(-r + f + br)

            // push the new r into every CTA's next buffer (incl. own)
            unsigned laddr = (unsigned)__cvta_generic_to_shared(&rbuf[pn][rb][jg]);
            #pragma unroll
            for (int rk = 0; rk < CSIZE; rk++) {
                unsigned raddr;
                asm("mapa.shared::cluster.u32 %0, %1, %2;"
                    : "=r"(raddr) : "r"(laddr), "r"(rk));
                asm volatile("st.shared::cluster.f32 [%0], %1;"
                             :: "r"(raddr), "f"(rn) : "memory");
            }
            // fire-and-forget history write (only read after kernel ends)
            g_rstore[(((size_t)(b0 + rb)) * TT + t) * RR + jg] = rn;
        }

        // ---- cluster barrier: release DSMEM pushes, acquire peers' ----
        asm volatile("barrier.cluster.arrive.aligned;" ::: "memory");
        asm volatile("barrier.cluster.wait.aligned;"   ::: "memory");

        p = pn;
    }
}

// ---------------------------------------------------------------------------
// Output GEMM: y[m][o] = by[o] + sum_k rstore[m][k] * Wyr[o][k]
// ---------------------------------------------------------------------------
#define YBM 64
#define YBK 32

__global__ void __launch_bounds__(256)
ctrnn_y(const float* __restrict__ g_rstore,  // [64000][512]
        const float* __restrict__ g_Wyr,     // [64][512]
        const float* __restrict__ g_by,      // [64]
        float* __restrict__ g_y)             // [64000][64]
{
    __shared__ float As[YBM][36];    // [m][k], pad for conflict-free col reads
    __shared__ float Bs[YBK][OO];    // [k][n]

    const int tid = threadIdx.x;
    const int m0  = blockIdx.x * YBM;
    const int tx  = tid & 15;        // n-group (4 cols)
    const int ty  = tid >> 4;        // m-group (4 rows)

    unsigned long long acc[4][2];
    #pragma unroll
    for (int i = 0; i < 4; i++) { acc[i][0] = 0ull; acc[i][1] = 0ull; }

    for (int k0 = 0; k0 < RR; k0 += YBK) {
        #pragma unroll
        for (int q = 0; q < 2; q++) {
            int idx = tid * 2 + q;
            int m   = idx >> 3;
            int kq  = idx & 7;
            float4 v = *(const float4*)(g_rstore + (size_t)(m0 + m) * RR + k0 + kq * 4);
            *(float4*)&As[m][kq * 4] = v;
        }
        #pragma unroll
        for (int q = 0; q < 2; q++) {
            int n  = tid >> 2;
            int kq = (tid & 3) * 2 + q;
            float4 v = *(const float4*)(g_Wyr + (size_t)n * RR + k0 + kq * 4);
            Bs[kq*4+0][n] = v.x;
            Bs[kq*4+1][n] = v.y;
            Bs[kq*4+2][n] = v.z;
            Bs[kq*4+3][n] = v.w;
        }
        __syncthreads();

        #pragma unroll
        for (int k = 0; k < YBK; k++) {
            unsigned long long bp0 = *(const unsigned long long*)&Bs[k][tx * 4];
            unsigned long long bp1 = *(const unsigned long long*)&Bs[k][tx * 4 + 2];
            #pragma unroll
            for (int i = 0; i < 4; i++) {
                unsigned au = __float_as_uint(As[ty * 4 + i][k]);
                unsigned long long ap;
                asm("mov.b64 %0,{%1,%1};" : "=l"(ap) : "r"(au));
                asm("fma.rn.f32x2 %0,%1,%2,%0;" : "+l"(acc[i][0]) : "l"(ap), "l"(bp0));
                asm("fma.rn.f32x2 %0,%1,%2,%0;" : "+l"(acc[i][1]) : "l"(ap), "l"(bp1));
            }
        }
        __syncthreads();
    }

    float by0 = g_by[tx * 4 + 0];
    float by1 = g_by[tx * 4 + 1];
    float by2 = g_by[tx * 4 + 2];
    float by3 = g_by[tx * 4 + 3];
    #pragma unroll
    for (int i = 0; i < 4; i++) {
        unsigned u0, u1, u2, u3;
        asm("mov.b64 {%0,%1},%2;" : "=r"(u0), "=r"(u1) : "l"(acc[i][0]));
        asm("mov.b64 {%0,%1},%2;" : "=r"(u2), "=r"(u3) : "l"(acc[i][1]));
        float4 out = make_float4(__uint_as_float(u0) + by0,
                                 __uint_as_float(u1) + by1,
                                 __uint_as_float(u2) + by2,
                                 __uint_as_float(u3) + by3);
        *(float4*)(g_y + (size_t)(m0 + ty * 4 + i) * OO + tx * 4) = out;
    }
}

// 4th launch so ncu's "-s 5 -c 1" lands on the second half-scan next round.
__global__ void ctrnn_nop() {}

// ---------------------------------------------------------------------------
// Launch: two half-scans (profilability) then output GEMM, then nop.
// Output layout: [ y (B*T*OO) | rstore (B*T*RR) ]
// ---------------------------------------------------------------------------
extern "C" void kernel_launch(void* const* d_in, const int* in_sizes, int n_in,
                              void* d_out, int out_size)
{
    const float* input = (const float*)d_in[0];
    const float* br    = (const float*)d_in[1];
    const float* Wrx   = (const float*)d_in[2];
    const float* bx    = (const float*)d_in[3];
    const float* Wrr   = (const float*)d_in[4];
    const float* Wyr   = (const float*)d_in[5];
    const float* by    = (const float*)d_in[6];
    const float* r0    = (const float*)d_in[7];

    float* y      = (float*)d_out;
    float* rstore = (float*)d_out + (size_t)BB * TT * OO;

    dim3 grid(CSIZE, NCLUS, 1);
    ctrnn_scan<<<grid, NTHR>>>(input, br, Wrx, bx, Wrr, r0, rstore, 0, TT / 2);
    ctrnn_scan<<<grid, NTHR>>>(input, br, Wrx, bx, Wrr, r0, rstore, TT / 2, TT);
    ctrnn_y<<<(BB * TT) / YBM, 256>>>(rstore, Wyr, by, y);
    ctrnn_nop<<<1, 32>>>();
}

// round 4
// speedup vs baseline: 1.0343x; 1.0261x over previous
#include <cuda_runtime.h>
#include <cstdint>
#include <cstddef>

// Problem constants
#define BB   64
#define TT   1000
#define DI   128
#define RR   512
#define OO   64
#define ALPHA 0.1f            // DT/TAU

// Scan layout: 16 clusters x 8 CTAs, 4 batches/cluster, 64 neurons/CTA
#define CSIZE 8
#define NCLUS 16
#define BPC   4
#define NTHR  512

__device__ __forceinline__ void ffma2(unsigned long long& acc,
                                      unsigned long long w,
                                      unsigned long long r) {
    asm("fma.rn.f32x2 %0,%1,%2,%0;" : "+l"(acc) : "l"(w), "l"(r));
}
__device__ __forceinline__ float unpack_sum(unsigned long long v) {
    unsigned lo, hi;
    asm("mov.b64 {%0,%1}, %2;" : "=r"(lo), "=r"(hi) : "l"(v));
    return __uint_as_float(lo) + __uint_as_float(hi);
}

// ---------------------------------------------------------------------------
// Persistent scan: one cluster = 4 batches, full T=1000 recurrence.
// CTA rank w owns neurons [64w,64w+64). Thread = (2 neurons, 32-k slice).
// Wrr/Wrx slices pre-packed as f32x2 pairs in registers. r is CTA-private
// SMEM [b][k]; new-r exchange: stage own slice in snew (double-buffered),
// cluster barrier (release/acquire), each thread pulls ONE float4 from the
// owning CTA via ld.shared::cluster.
// ---------------------------------------------------------------------------
__global__ void __cluster_dims__(CSIZE, 1, 1) __launch_bounds__(NTHR, 1)
ctrnn_scan(const float* __restrict__ g_in,   // [B][T][DI]
           const float* __restrict__ g_br,   // [B][T][RR]
           const float* __restrict__ g_Wrx,  // [RR][DI]
           const float* __restrict__ g_bx,   // [RR]
           const float* __restrict__ g_Wrr,  // [RR][RR]
           const float* __restrict__ g_r0,   // [RR]
           float* __restrict__ g_rstore)     // [B][T][RR]
{
    __shared__ __align__(16) float rbuf[BPC][RR];        //  8 KB (CTA-private)
    __shared__ __align__(16) float sInp[BPC][DI];        //  2 KB
    __shared__ __align__(16) float pz[16][BPC][64];      // 16 KB partials
    __shared__ __align__(16) float snew[2][BPC][64];     //  2 KB exchange stage

    const int w   = blockIdx.x;      // cluster rank 0..7
    const int c   = blockIdx.y;      // cluster id 0..15
    const int tid = threadIdx.x;
    const int jp  = tid & 31;        // neuron-pair index 0..31
    const int kg  = tid >> 5;        // k-group 0..15 (32 k each)
    const int j0  = jp * 2;          // first local neuron of the pair
    const int jg0 = w * 64 + j0;     // global neuron
    const int b0  = c * BPC;         // first batch of this cluster

    // ---- one-time: weight slices into registers as packed f32x2 pairs ----
    unsigned long long wrrp[2][16];
    #pragma unroll
    for (int jj = 0; jj < 2; jj++) {
        const ulonglong2* src =
            (const ulonglong2*)(g_Wrr + (size_t)(jg0 + jj) * RR + kg * 32);
        #pragma unroll
        for (int q = 0; q < 8; q++) {
            ulonglong2 v = src[q];
            wrrp[jj][2*q+0] = v.x;
            wrrp[jj][2*q+1] = v.y;
        }
    }
    unsigned long long wrxp[2][4];
    #pragma unroll
    for (int jj = 0; jj < 2; jj++) {
        const ulonglong2* src =
            (const ulonglong2*)(g_Wrx + (size_t)(jg0 + jj) * DI + kg * 8);
        #pragma unroll
        for (int q = 0; q < 2; q++) {
            ulonglong2 v = src[q];
            wrxp[jj][2*q+0] = v.x;
            wrxp[jj][2*q+1] = v.y;
        }
    }

    // role indices
    const int rb   = tid >> 6;        // reducer batch (tid<256)
    const int rj   = tid & 63;        // reducer neuron
    const float bxr = g_bx[w * 64 + rj];
    const int sb_i = tid >> 5;        // input-stage batch (tid<128)
    const int si4  = tid & 31;        // input-stage float4 chunk
    // pull indices
    const int pb   = tid >> 7;        // batch 0..3
    const int pk4  = tid & 127;       // float4 index into 512
    const int prank = pk4 >> 4;       // owning CTA rank
    const int pj4   = pk4 & 15;       // float4 within owner's 64 neurons

    // ---- init rbuf from r0 ----
    {
        float v = g_r0[tid];
        #pragma unroll
        for (int b = 0; b < BPC; b++) rbuf[b][tid] = v;
    }
    // stage input t=0
    if (tid < 128)
        *(float4*)&sInp[sb_i][si4 * 4] =
            *(const float4*)(g_in + (((size_t)(b0 + sb_i)) * TT + 0) * DI + si4 * 4);
    __syncthreads();

    // prefetch input t=1
    float4 nxt_in = make_float4(0.f, 0.f, 0.f, 0.f);
    if (tid < 128)
        nxt_in = *(const float4*)(g_in + (((size_t)(b0 + sb_i)) * TT + 1) * DI + si4 * 4);

    const ulonglong2* ru = (const ulonglong2*)rbuf;   // [b*128 + k4]
    const ulonglong2* su = (const ulonglong2*)sInp;   // [b*32  + i4]

    int sb = 0;
    for (int t = 0; t < TT; t++) {
        // prefetch br[t] for the reduce phase
        float brv = 0.f;
        if (tid < 256)
            brv = g_br[(((size_t)(b0 + rb)) * TT + t) * RR + w * 64 + rj];

        // ---- main matvec: 2 neurons x 32 k x 4 batches per thread ----
        unsigned long long acc0[4] = {0ull,0ull,0ull,0ull};
        unsigned long long acc1[4] = {0ull,0ull,0ull,0ull};
        {
            const int kb = kg * 8;   // ulonglong2 base within 128 per batch
            #pragma unroll
            for (int ch = 0; ch < 8; ch++) {
                #pragma unroll
                for (int b = 0; b < 4; b++) {
                    ulonglong2 rv = ru[b * 128 + kb + ch];
                    ffma2(acc0[b], wrrp[0][2*ch+0], rv.x);
                    ffma2(acc0[b], wrrp[0][2*ch+1], rv.y);
                    ffma2(acc1[b], wrrp[1][2*ch+0], rv.x);
                    ffma2(acc1[b], wrrp[1][2*ch+1], rv.y);
                }
            }
            const int ib = kg * 2;   // ulonglong2 base within 32 per batch
            #pragma unroll
            for (int ch = 0; ch < 2; ch++) {
                #pragma unroll
                for (int b = 0; b < 4; b++) {
                    ulonglong2 iv = su[b * 32 + ib + ch];
                    ffma2(acc0[b], wrxp[0][2*ch+0], iv.x);
                    ffma2(acc0[b], wrxp[0][2*ch+1], iv.y);
                    ffma2(acc1[b], wrxp[1][2*ch+0], iv.x);
                    ffma2(acc1[b], wrxp[1][2*ch+1], iv.y);
                }
            }
        }
        #pragma unroll
        for (int b = 0; b < 4; b++) {
            pz[kg][b][j0 + 0] = unpack_sum(acc0[b]);
            pz[kg][b][j0 + 1] = unpack_sum(acc1[b]);
        }
        __syncthreads();

        // ---- reduce 16 k-groups, retanh, leaky update, stage + store ----
        if (tid < 256) {
            float s = bxr;
            float s0 = 0.f, s1 = 0.f;
            #pragma unroll
            for (int g = 0; g < 16; g += 2) {
                s0 += pz[g][rb][rj];
                s1 += pz[g+1][rb][rj];
            }
            float z = s + s0 + s1;
            float f = (z > 0.f) ? tanhf(z) : 0.f;            // retanh
            float rold = rbuf[rb][w * 64 + rj];
            float rn = fmaf(ALPHA, f + brv - rold, rold);    // r + a*(-r+f+br)
            snew[sb][rb][rj] = rn;
            // fire-and-forget history (read only by ctrnn_y afterwards)
            g_rstore[(((size_t)(b0 + rb)) * TT + t) * RR + w * 64 + rj] = rn;
        }

        // ---- cluster barrier: release snew, acquire peers' snew ----
        asm volatile("barrier.cluster.arrive.aligned;" ::: "memory");
        asm volatile("barrier.cluster.wait.aligned;"   ::: "memory");

        // ---- pull the full new r: one remote float4 per thread ----
        {
            unsigned laddr = (unsigned)__cvta_generic_to_shared(
                                 &snew[sb][pb][pj4 * 4]);
            unsigned raddr;
            asm("mapa.shared::cluster.u32 %0, %1, %2;"
                : "=r"(raddr) : "r"(laddr), "r"(prank));
            float x, y2, z2, w2;
            asm volatile("ld.shared::cluster.v4.f32 {%0,%1,%2,%3},[%4];"
                         : "=f"(x), "=f"(y2), "=f"(z2), "=f"(w2) : "r"(raddr));
            *(float4*)&rbuf[pb][pk4 * 4] = make_float4(x, y2, z2, w2);
        }
        // stage input t+1; prefetch t+2
        if (tid < 128) {
            *(float4*)&sInp[sb_i][si4 * 4] = nxt_in;
            if (t + 2 < TT)
                nxt_in = *(const float4*)(g_in +
                    (((size_t)(b0 + sb_i)) * TT + (t + 2)) * DI + si4 * 4);
        }
        __syncthreads();
        sb ^= 1;
    }
}

// ---------------------------------------------------------------------------
// Output GEMM: y[m][o] = by[o] + sum_k rstore[m][k] * Wyr[o][k]
// ---------------------------------------------------------------------------
#define YBM 64
#define YBK 32

__global__ void __launch_bounds__(256)
ctrnn_y(const float* __restrict__ g_rstore,  // [64000][512]
        const float* __restrict__ g_Wyr,     // [64][512]
        const float* __restrict__ g_by,      // [64]
        float* __restrict__ g_y)             // [64000][64]
{
    __shared__ float As[YBM][36];    // [m][k], pad for conflict-free col reads
    __shared__ float Bs[YBK][OO];    // [k][n]

    const int tid = threadIdx.x;
    const int m0  = blockIdx.x * YBM;
    const int tx  = tid & 15;        // n-group (4 cols)
    const int ty  = tid >> 4;        // m-group (4 rows)

    unsigned long long acc[4][2];
    #pragma unroll
    for (int i = 0; i < 4; i++) { acc[i][0] = 0ull; acc[i][1] = 0ull; }

    for (int k0 = 0; k0 < RR; k0 += YBK) {
        #pragma unroll
        for (int q = 0; q < 2; q++) {
            int idx = tid * 2 + q;
            int m   = idx >> 3;
            int kq  = idx & 7;
            float4 v = *(const float4*)(g_rstore + (size_t)(m0 + m) * RR + k0 + kq * 4);
            *(float4*)&As[m][kq * 4] = v;
        }
        #pragma unroll
        for (int q = 0; q < 2; q++) {
            int n  = tid >> 2;
            int kq = (tid & 3) * 2 + q;
            float4 v = *(const float4*)(g_Wyr + (size_t)n * RR + k0 + kq * 4);
            Bs[kq*4+0][n] = v.x;
            Bs[kq*4+1][n] = v.y;
            Bs[kq*4+2][n] = v.z;
            Bs[kq*4+3][n] = v.w;
        }
        __syncthreads();

        #pragma unroll
        for (int k = 0; k < YBK; k++) {
            unsigned long long bp0 = *(const unsigned long long*)&Bs[k][tx * 4];
            unsigned long long bp1 = *(const unsigned long long*)&Bs[k][tx * 4 + 2];
            #pragma unroll
            for (int i = 0; i < 4; i++) {
                unsigned au = __float_as_uint(As[ty * 4 + i][k]);
                unsigned long long ap;
                asm("mov.b64 %0,{%1,%1};" : "=l"(ap) : "r"(au));
                ffma2(acc[i][0], ap, bp0);
                ffma2(acc[i][1], ap, bp1);
            }
        }
        __syncthreads();
    }

    float by0 = g_by[tx * 4 + 0];
    float by1 = g_by[tx * 4 + 1];
    float by2 = g_by[tx * 4 + 2];
    float by3 = g_by[tx * 4 + 3];
    #pragma unroll
    for (int i = 0; i < 4; i++) {
        unsigned u0, u1, u2, u3;
        asm("mov.b64 {%0,%1},%2;" : "=r"(u0), "=r"(u1) : "l"(acc[i][0]));
        asm("mov.b64 {%0,%1},%2;" : "=r"(u2), "=r"(u3) : "l"(acc[i][1]));
        float4 out = make_float4(__uint_as_float(u0) + by0,
                                 __uint_as_float(u1) + by1,
                                 __uint_as_float(u2) + by2,
                                 __uint_as_float(u3) + by3);
        *(float4*)(g_y + (size_t)(m0 + ty * 4 + i) * OO + tx * 4) = out;
    }
}

// Padding so ncu's "-s 5 -c 1" lands on launch #6 = ctrnn_scan of call 2.
__global__ void ctrnn_nop() {}

// ---------------------------------------------------------------------------
// Output layout: [ y (B*T*OO) | rstore (B*T*RR) ]
// ---------------------------------------------------------------------------
extern "C" void kernel_launch(void* const* d_in, const int* in_sizes, int n_in,
                              void* d_out, int out_size)
{
    const float* input = (const float*)d_in[0];
    const float* br    = (const float*)d_in[1];
    const float* Wrx   = (const float*)d_in[2];
    const float* bx    = (const float*)d_in[3];
    const float* Wrr   = (const float*)d_in[4];
    const float* Wyr   = (const float*)d_in[5];
    const float* by    = (const float*)d_in[6];
    const float* r0    = (const float*)d_in[7];

    float* y      = (float*)d_out;
    float* rstore = (float*)d_out + (size_t)BB * TT * OO;

    dim3 grid(CSIZE, NCLUS, 1);
    ctrnn_scan<<<grid, NTHR>>>(input, br, Wrx, bx, Wrr, r0, rstore);
    ctrnn_y<<<(BB * TT) / YBM, 256>>>(rstore, Wyr, by, y);
    ctrnn_nop<<<1, 32>>>();
    ctrnn_nop<<<1, 32>>>();
    ctrnn_nop<<<1, 32>>>();
}

// round 5
// speedup vs baseline: 1.4458x; 1.3979x over previous
#include <cuda_runtime.h>
#include <cstdint>
#include <cstddef>

// Problem constants
#define BB   64
#define TT   1000
#define DI   128
#define RR   512
#define OO   64
#define ALPHA 0.1f            // DT/TAU

// Scan layout: 16 clusters x 8 CTAs, 4 batches/cluster, 64 neurons/CTA
#define CSIZE 8
#define NCLUS 16
#define BPC   4
#define NTHR  512

// Scratch: precomputed input drive x_drive = input @ Wrx^T + bx  [B][T][RR]
__device__ float g_xd[(size_t)BB * TT * RR];   // 131 MB

__device__ __forceinline__ void ffma2(unsigned long long& acc,
                                      unsigned long long w,
                                      unsigned long long r) {
    asm("fma.rn.f32x2 %0,%1,%2,%0;" : "+l"(acc) : "l"(w), "l"(r));
}
__device__ __forceinline__ float unpack_sum(unsigned long long v) {
    unsigned lo, hi;
    asm("mov.b64 {%0,%1}, %2;" : "=r"(lo), "=r"(hi) : "l"(v));
    return __uint_as_float(lo) + __uint_as_float(hi);
}

// ---------------------------------------------------------------------------
// Generic small-N GEMM used for both x_drive precompute and the output GEMM:
//   out[m][n0+n] = bias[n0+n] + sum_k A[m][k] * W[n0+n][k]
// A: [M][K] row-major, W: [N][K] row-major. Tile: 64m x 64n, K-step 32.
// ---------------------------------------------------------------------------
template<int K, int OUTSTRIDE>
__global__ void __launch_bounds__(256)
gemm_nt(const float* __restrict__ g_A,
        const float* __restrict__ g_W,
        const float* __restrict__ g_bias,
        float* __restrict__ g_out)
{
    __shared__ float As[64][36];     // [m][k] (two 32-k halves), padded
    __shared__ float Bs[32][64];     // [k][n]

    const int tid = threadIdx.x;
    const int m0  = blockIdx.x * 64;
    const int n0  = blockIdx.y * 64;
    const int tx  = tid & 15;        // n-group (4 cols)
    const int ty  = tid >> 4;        // m-group (4 rows)

    unsigned long long acc[4][2];
    #pragma unroll
    for (int i = 0; i < 4; i++) { acc[i][0] = 0ull; acc[i][1] = 0ull; }

    for (int k0 = 0; k0 < K; k0 += 32) {
        #pragma unroll
        for (int q = 0; q < 2; q++) {
            int idx = tid * 2 + q;
            int m   = idx >> 3;
            int kq  = idx & 7;
            float4 v = *(const float4*)(g_A + (size_t)(m0 + m) * K + k0 + kq * 4);
            *(float4*)&As[m][kq * 4] = v;
        }
        #pragma unroll
        for (int q = 0; q < 2; q++) {
            int n  = tid >> 2;
            int kq = (tid & 3) * 2 + q;
            float4 v = *(const float4*)(g_W + (size_t)(n0 + n) * K + k0 + kq * 4);
            Bs[kq*4+0][n] = v.x;
            Bs[kq*4+1][n] = v.y;
            Bs[kq*4+2][n] = v.z;
            Bs[kq*4+3][n] = v.w;
        }
        __syncthreads();

        #pragma unroll
        for (int k = 0; k < 32; k++) {
            unsigned long long bp0 = *(const unsigned long long*)&Bs[k][tx * 4];
            unsigned long long bp1 = *(const unsigned long long*)&Bs[k][tx * 4 + 2];
            #pragma unroll
            for (int i = 0; i < 4; i++) {
                unsigned au = __float_as_uint(As[ty * 4 + i][k]);
                unsigned long long ap;
                asm("mov.b64 %0,{%1,%1};" : "=l"(ap) : "r"(au));
                ffma2(acc[i][0], ap, bp0);
                ffma2(acc[i][1], ap, bp1);
            }
        }
        __syncthreads();
    }

    float b0v = g_bias[n0 + tx * 4 + 0];
    float b1v = g_bias[n0 + tx * 4 + 1];
    float b2v = g_bias[n0 + tx * 4 + 2];
    float b3v = g_bias[n0 + tx * 4 + 3];
    #pragma unroll
    for (int i = 0; i < 4; i++) {
        unsigned u0, u1, u2, u3;
        asm("mov.b64 {%0,%1},%2;" : "=r"(u0), "=r"(u1) : "l"(acc[i][0]));
        asm("mov.b64 {%0,%1},%2;" : "=r"(u2), "=r"(u3) : "l"(acc[i][1]));
        float4 out = make_float4(__uint_as_float(u0) + b0v,
                                 __uint_as_float(u1) + b1v,
                                 __uint_as_float(u2) + b2v,
                                 __uint_as_float(u3) + b3v);
        *(float4*)(g_out + (size_t)(m0 + ty * 4 + i) * OUTSTRIDE + n0 + tx * 4) = out;
    }
}

// helper so the scan can take g_xd as a plain pointer
__global__ void xd_noop() {}

// ---------------------------------------------------------------------------
// Persistent scan: one cluster = 4 batches, full T=1000 recurrence.
// CTA rank w owns neurons [64w,64w+64). Thread = (2 neurons, 32-k slice).
// Wrr slice pre-packed as f32x2 pairs in registers (64 regs — no Wrx, no
// input staging; x_drive is precomputed and streamed like br).
// Exchange: reducers stage new r in snew (double-buffered), cluster barrier,
// every thread pulls one float4 from the owning CTA via ld.shared::cluster.
// rstore STG issued AFTER the barrier so its drain overlaps the next GEMM.
// ---------------------------------------------------------------------------
__global__ void __cluster_dims__(CSIZE, 1, 1) __launch_bounds__(NTHR, 1)
ctrnn_scan(const float* __restrict__ g_br,   // [B][T][RR]
           const float* __restrict__ g_Wrr,  // [RR][RR]
           const float* __restrict__ g_r0,   // [RR]
           float* __restrict__ g_rstore)     // [B][T][RR]
{
    __shared__ __align__(16) float rbuf[BPC][RR];        //  8 KB
    __shared__ __align__(16) float pz[16][BPC][64];      // 16 KB
    __shared__ __align__(16) float snew[2][BPC][64];     //  2 KB

    const int w   = blockIdx.x;      // cluster rank 0..7
    const int c   = blockIdx.y;      // cluster id 0..15
    const int tid = threadIdx.x;
    const int jp  = tid & 31;        // neuron-pair index
    const int kg  = tid >> 5;        // k-group 0..15 (32 k each)
    const int j0  = jp * 2;
    const int jg0 = w * 64 + j0;
    const int b0  = c * BPC;

    // ---- one-time: Wrr slice into registers as packed f32x2 pairs ----
    unsigned long long wrrp[2][16];
    #pragma unroll
    for (int jj = 0; jj < 2; jj++) {
        const ulonglong2* src =
            (const ulonglong2*)(g_Wrr + (size_t)(jg0 + jj) * RR + kg * 32);
        #pragma unroll
        for (int q = 0; q < 8; q++) {
            ulonglong2 v = src[q];
            wrrp[jj][2*q+0] = v.x;
            wrrp[jj][2*q+1] = v.y;
        }
    }

    // role indices
    const int rb = tid >> 6;          // reducer batch (tid<256)
    const int rj = tid & 63;          // reducer neuron
    const size_t rrow = ((size_t)(b0 + rb)) * TT;   // row base for br/xd/rstore
    // pull indices
    const int pb    = tid >> 7;       // batch 0..3
    const int pk4   = tid & 127;      // float4 index into 512
    const int prank = pk4 >> 4;       // owning CTA rank
    const int pj4   = pk4 & 15;       // float4 within owner's 64 neurons

    // ---- init rbuf from r0 ----
    {
        float v = g_r0[tid];
        #pragma unroll
        for (int b = 0; b < BPC; b++) rbuf[b][tid] = v;
    }
    __syncthreads();

    const ulonglong2* ru = (const ulonglong2*)rbuf;   // [b*128 + k4]

    int sb = 0;
    for (int t = 0; t < TT; t++) {
        // prefetch br[t] and xd[t] for the reduce phase
        float brv = 0.f, xdv = 0.f;
        if (tid < 256) {
            brv = g_br[(rrow + t) * RR + w * 64 + rj];
            xdv = g_xd[(rrow + t) * RR + w * 64 + rj];
        }

        // ---- main matvec: 2 neurons x 32 k x 4 batches per thread ----
        unsigned long long acc0[4] = {0ull,0ull,0ull,0ull};
        unsigned long long acc1[4] = {0ull,0ull,0ull,0ull};
        {
            const int kb = kg * 8;   // ulonglong2 base within 128 per batch
            #pragma unroll
            for (int ch = 0; ch < 8; ch++) {
                #pragma unroll
                for (int b = 0; b < 4; b++) {
                    ulonglong2 rv = ru[b * 128 + kb + ch];
                    ffma2(acc0[b], wrrp[0][2*ch+0], rv.x);
                    ffma2(acc0[b], wrrp[0][2*ch+1], rv.y);
                    ffma2(acc1[b], wrrp[1][2*ch+0], rv.x);
                    ffma2(acc1[b], wrrp[1][2*ch+1], rv.y);
                }
            }
        }
        #pragma unroll
        for (int b = 0; b < 4; b++) {
            pz[kg][b][j0 + 0] = unpack_sum(acc0[b]);
            pz[kg][b][j0 + 1] = unpack_sum(acc1[b]);
        }
        __syncthreads();

        // ---- reduce 16 k-groups, retanh, leaky update, stage ----
        float rn = 0.f;
        if (tid < 256) {
            float s0 = 0.f, s1 = 0.f;
            #pragma unroll
            for (int g = 0; g < 16; g += 2) {
                s0 += pz[g][rb][rj];
                s1 += pz[g+1][rb][rj];
            }
            float z = xdv + s0 + s1;
            float f = (z > 0.f) ? tanhf(z) : 0.f;            // retanh
            float rold = rbuf[rb][w * 64 + rj];
            rn = fmaf(ALPHA, f + brv - rold, rold);          // r + a*(-r+f+br)
            snew[sb][rb][rj] = rn;
        }

        // ---- cluster barrier: release snew, acquire peers' snew ----
        asm volatile("barrier.cluster.arrive.aligned;" ::: "memory");
        asm volatile("barrier.cluster.wait.aligned;"   ::: "memory");

        // history write AFTER the barrier: drain overlaps the next GEMM
        if (tid < 256)
            g_rstore[(rrow + t) * RR + w * 64 + rj] = rn;

        // ---- pull the full new r: one remote float4 per thread ----
        {
            unsigned laddr = (unsigned)__cvta_generic_to_shared(
                                 &snew[sb][pb][pj4 * 4]);
            unsigned raddr;
            asm("mapa.shared::cluster.u32 %0, %1, %2;"
                : "=r"(raddr) : "r"(laddr), "r"(prank));
            float x, y2, z2, w2;
            asm volatile("ld.shared::cluster.v4.f32 {%0,%1,%2,%3},[%4];"
                         : "=f"(x), "=f"(y2), "=f"(z2), "=f"(w2) : "r"(raddr));
            *(float4*)&rbuf[pb][pk4 * 4] = make_float4(x, y2, z2, w2);
        }
        __syncthreads();
        sb ^= 1;
    }
}

__global__ void ctrnn_nop() {}

// ---------------------------------------------------------------------------
// Output layout: [ y (B*T*OO) | rstore (B*T*RR) ]
// ---------------------------------------------------------------------------
extern "C" void kernel_launch(void* const* d_in, const int* in_sizes, int n_in,
                              void* d_out, int out_size)
{
    const float* input = (const float*)d_in[0];
    const float* br    = (const float*)d_in[1];
    const float* Wrx   = (const float*)d_in[2];
    const float* bx    = (const float*)d_in[3];
    const float* Wrr   = (const float*)d_in[4];
    const float* Wyr   = (const float*)d_in[5];
    const float* by    = (const float*)d_in[6];
    const float* r0    = (const float*)d_in[7];

    float* y      = (float*)d_out;
    float* rstore = (float*)d_out + (size_t)BB * TT * OO;

    float* xd = nullptr;
    cudaGetSymbolAddress((void**)&xd, g_xd);

    // 1) x_drive = input @ Wrx^T + bx   [64000 x 512], K=128
    {
        dim3 g((BB * TT) / 64, RR / 64);
        gemm_nt<DI, RR><<<g, 256>>>(input, Wrx, bx, xd);
    }
    // 2) recurrence
    {
        dim3 grid(CSIZE, NCLUS, 1);
        ctrnn_scan<<<grid, NTHR>>>(br, Wrr, r0, rstore);
    }
    // 3) y = rstore @ Wyr^T + by        [64000 x 64], K=512
    {
        dim3 g((BB * TT) / 64, OO / 64);
        gemm_nt<RR, OO><<<g, 256>>>(rstore, Wyr, by, y);
    }
    ctrnn_nop<<<1, 32>>>();
    ctrnn_nop<<<1, 32>>>();
}